// round 15
// baseline (speedup 1.0000x reference)
#include <cuda_runtime.h>
#include <cuda.h>
#include <cuda_fp16.h>
#include <cstdint>

// ---------------------------------------------------------------------------
// TPAsyncDense, persistent 4-CTA clusters (2 cg2 pairs), fp16 GEMM, KB=128:
//   y[d] = sum_i x_i @ W[d,i] + b[d]
// R15 = R14 (KB=128 chunks, best 244us) + R13's cluster-4 B-multicast.
// Measured: R14's 3-stage pipeline leaks cycles because a 64KB stage refill
// (~2100 cyc at ~41 B/cyc/CTA L2->SMEM service) slightly exceeds the 2-chunk
// MMA window (2048 cyc). Multicasting B across cg2 pairs (masks 0x5/0xA)
// cuts per-cluster chunk traffic 256->192 KB -> refill ~1770 cyc < window.
// Cluster: pairs {0,1},{2,3} compute m-adjacent 256x256 tiles of one (n,d).
// TMEM 2x256 ping-pong per pair. Grid 144 = 36 clusters.
// ---------------------------------------------------------------------------

#if defined(__CUDA_ARCH_FEAT_SM103_ALL) || defined(__CUDA_ARCH_FEAT_SM100_ALL) || \
    defined(__CUDA_ARCH_SPECIFIC__) || defined(__CUDA_ARCH_FAMILY_SPECIFIC__)
#define TC_OK 1
#else
#define TC_OK 0
#endif

#define M_TOT 8192
#define N_TOT 2048
#define K_TOT 2048
#define D_TOT 4

#define KB 128                     // K elems per chunk (2 SW128 subtiles)
#define NCHUNK 16                  // 2048/128
#define STAGES 3
#define NPAIRS (D_TOT * (M_TOT / 512) * (N_TOT / 256))   // 512

#define OFF_TMEM     0
#define OFF_FULL     16            // 3 x 8B
#define OFF_EMPTY    48            // 3 x 8B
#define OFF_ACCDONE  80            // 2 x 8B
#define OFF_ACCFREE  96            // 2 x 8B
#define HALF_BYTES   16384         // one 64-wide SW128 subtile (128 rows)
#define OP_BYTES     (2 * HALF_BYTES)               // 32768 per operand
#define STG_BYTES    (2 * OP_BYTES)                 // 65536 {A, B}
#define OFF_STG      1024
#define SMEM_TOTAL   (OFF_STG + STAGES * STG_BYTES) // 197632
#define CHUNK_TX     (6 * HALF_BYTES)               // leader: A cg2 64K + B 32K

#define SO_A 0
#define SO_B OP_BYTES

// cg2 idesc: dtype=F32(1<<4), atype=btype=FP16(0), N=256, M=256
#define IDESC_F16 ((1u<<4) | (32u<<17) | (16u<<24))

static constexpr uint64_t DESC_BASE_SW128 =
    (uint64_t(2) << 61) | (uint64_t(1) << 46) | (uint64_t(64) << 32) | (uint64_t(1) << 16);
// k-step desc offset: steps 0-3 in first 16KB subtile (+2), steps 4-7 in
// second subtile (+1024 units = 16KB)
__device__ __forceinline__ uint64_t kstep_off(int ks) {
    return (uint64_t)((ks >> 2) * 1024 + (ks & 3) * 2);
}

// ------------------------- scratch (static device mem) ---------------------
__device__ __align__(1024) __half g_A16[(size_t)M_TOT * K_TOT];
__device__ __align__(1024) __half g_B16[(size_t)D_TOT * N_TOT * K_TOT];

// ------------------------------ PTX helpers --------------------------------
__device__ __forceinline__ uint32_t smem_u32(const void* p) {
    uint32_t a;
    asm("{ .reg .u64 t; cvta.to.shared.u64 t, %1; cvt.u32.u64 %0, t; }" : "=r"(a) : "l"(p));
    return a;
}
__device__ __forceinline__ uint32_t elect_one() {
    uint32_t pred;
    asm volatile("{\n\t.reg .pred p;\n\telect.sync _|p, 0xFFFFFFFF;\n\tselp.b32 %0, 1, 0, p;\n\t}"
                 : "=r"(pred));
    return pred;
}
__device__ __forceinline__ uint32_t cluster_rank() {
    uint32_t r;
    asm("mov.u32 %0, %%cluster_ctarank;" : "=r"(r));
    return r;
}
#define CLUSTER_SYNC() do { \
    asm volatile("barrier.cluster.arrive.aligned;" ::: "memory"); \
    asm volatile("barrier.cluster.wait.aligned;" ::: "memory"); \
} while (0)

#define MBAR_INIT(addr, cnt) \
    asm volatile("mbarrier.init.shared.b64 [%0], %1;" :: "r"(addr), "r"(cnt) : "memory")
#define MBAR_INVAL(addr) \
    asm volatile("mbarrier.inval.shared.b64 [%0];" :: "r"(addr) : "memory")
#define MBAR_EXPECT_TX(addr, bytes) \
    asm volatile("mbarrier.arrive.expect_tx.shared.b64 _, [%0], %1;" :: "r"(addr), "r"(bytes) : "memory")
#define MBAR_ARRIVE_RANK(addr, r) \
    asm volatile("{\n\t.reg .b32 ra;\n\tmapa.shared::cluster.u32 ra, %0, %1;\n\t" \
                 "mbarrier.arrive.shared::cluster.b64 _, [ra];\n\t}" \
                 :: "r"(addr), "r"(r) : "memory")

__device__ __forceinline__ void mbar_wait_acq(uint32_t mbar, uint32_t parity) {
    asm volatile(
        "{\n\t.reg .pred P1;\n\t"
        "WAIT_LOOP_%=:\n\t"
        "mbarrier.try_wait.parity.acquire.cta.shared::cta.b64 P1, [%0], %1, 0x989680;\n\t"
        "@P1 bra.uni WAIT_DONE_%=;\n\t"
        "bra.uni WAIT_LOOP_%=;\n\t"
        "WAIT_DONE_%=:\n\t}"
        :: "r"(mbar), "r"(parity) : "memory");
}
__device__ __forceinline__ void mbar_wait_rel(uint32_t mbar, uint32_t parity) {
    asm volatile(
        "{\n\t.reg .pred P1;\n\t"
        "WAIT_LOOP_%=:\n\t"
        "mbarrier.try_wait.parity.relaxed.cta.shared::cta.b64 P1, [%0], %1, 0x989680;\n\t"
        "@P1 bra.uni WAIT_DONE_%=;\n\t"
        "bra.uni WAIT_LOOP_%=;\n\t"
        "WAIT_DONE_%=:\n\t}"
        :: "r"(mbar), "r"(parity) : "memory");
}

#if TC_OK
// cg2 TMA (A): complete_tx targets the pair leader's barrier (bit 24 clear)
__device__ __forceinline__ void tma_load_cg2(uint32_t smem_dst, const CUtensorMap* map,
                                             int cx, int cy, int cz, uint32_t mbar) {
    asm volatile(
        "{\n\t.reg .b32 lb;\n\t"
        "and.b32 lb, %5, 0xFEFFFFFF;\n\t"
        "cp.async.bulk.tensor.3d.cta_group::2.shared::cluster.global"
        ".tile.mbarrier::complete_tx::bytes [%0], [%1, {%2, %3, %4}], [lb];\n\t}"
        :: "r"(smem_dst), "l"(map), "r"(cx), "r"(cy), "r"(cz), "r"(mbar) : "memory");
}
// multicast TMA (B): delivers data + complete_tx to every masked CTA's barrier
__device__ __forceinline__ void tma_mcast_3d(uint32_t smem_dst, const CUtensorMap* map,
                                             int cx, int cy, int cz, uint32_t mbar,
                                             uint16_t mask) {
    asm volatile(
        "cp.async.bulk.tensor.3d.shared::cluster.global.tile"
        ".mbarrier::complete_tx::bytes.multicast::cluster "
        "[%0], [%1, {%2, %3, %4}], [%5], %6;"
        :: "r"(smem_dst), "l"(map), "r"(cx), "r"(cy), "r"(cz), "r"(mbar), "h"(mask)
        : "memory");
}

__device__ __forceinline__ void mma_f16_cg2(uint32_t dtm, uint64_t adesc, uint64_t bdesc,
                                            uint32_t idesc, uint32_t en) {
    asm volatile(
        "{\n\t.reg .pred p;\n\tsetp.ne.u32 p, %5, 0;\n\t"
        "tcgen05.mma.cta_group::2.kind::f16 [%0], %1, %2, %3, "
        "{%4, %4, %4, %4, %4, %4, %4, %4}, p;\n\t}"
        :: "r"(dtm), "l"(adesc), "l"(bdesc), "r"(idesc), "r"(0u), "r"(en) : "memory");
}

#define TC_ALLOC_CG2(smem_addr, cols) \
    asm volatile("tcgen05.alloc.cta_group::2.sync.aligned.shared::cta.b32 [%0], %1;" \
                 :: "r"(smem_addr), "r"(cols) : "memory")
#define TC_DEALLOC_CG2(tmem, cols) \
    asm volatile("tcgen05.dealloc.cta_group::2.sync.aligned.b32 %0, %1;" :: "r"(tmem), "r"(cols))
#define TC_RELINQ_CG2() \
    asm volatile("tcgen05.relinquish_alloc_permit.cta_group::2.sync.aligned;")
#define TC_COMMIT_MC_CG2(mbar, mask) \
    asm volatile("tcgen05.commit.cta_group::2.mbarrier::arrive::one.shared::cluster" \
                 ".multicast::cluster.b64 [%0], %1;" \
                 :: "r"(mbar), "h"((uint16_t)(mask)) : "memory")
#define TC_FENCE_AFTER() asm volatile("tcgen05.fence::after_thread_sync;" ::: "memory")
#define TC_FENCE_BEFORE() asm volatile("tcgen05.fence::before_thread_sync;" ::: "memory")
#define TC_WAIT_LD() asm volatile("tcgen05.wait::ld.sync.aligned;" ::: "memory")

#define TC_LD_X32(r, tm) \
    asm volatile( \
        "tcgen05.ld.sync.aligned.32x32b.x32.b32 " \
        "{%0, %1, %2, %3, %4, %5, %6, %7, " \
        " %8, %9, %10, %11, %12, %13, %14, %15, " \
        " %16, %17, %18, %19, %20, %21, %22, %23, " \
        " %24, %25, %26, %27, %28, %29, %30, %31}, [%32];" \
        : "=r"((r)[0]),  "=r"((r)[1]),  "=r"((r)[2]),  "=r"((r)[3]), \
          "=r"((r)[4]),  "=r"((r)[5]),  "=r"((r)[6]),  "=r"((r)[7]), \
          "=r"((r)[8]),  "=r"((r)[9]),  "=r"((r)[10]), "=r"((r)[11]), \
          "=r"((r)[12]), "=r"((r)[13]), "=r"((r)[14]), "=r"((r)[15]), \
          "=r"((r)[16]), "=r"((r)[17]), "=r"((r)[18]), "=r"((r)[19]), \
          "=r"((r)[20]), "=r"((r)[21]), "=r"((r)[22]), "=r"((r)[23]), \
          "=r"((r)[24]), "=r"((r)[25]), "=r"((r)[26]), "=r"((r)[27]), \
          "=r"((r)[28]), "=r"((r)[29]), "=r"((r)[30]), "=r"((r)[31]) \
        : "r"(tm))
#endif // TC_OK

// ------------------------------ fused prep ---------------------------------
__global__ void prep_kernel(const float* __restrict__ x,
                            const float* __restrict__ W,
                            __half* __restrict__ A16,
                            __half* __restrict__ B16) {
    const int tid = threadIdx.x;
    if (blockIdx.x < 16384) {
        // x: [4][8192][512] f32 -> A16 fp16 [8192][2048] (K = shard*512 + k)
        size_t t = (size_t)blockIdx.x * 256 + tid;
        size_t e = t * 4;
        int i = (int)(e >> 22);
        int m = (int)((e >> 9) & 8191);
        int k = (int)(e & 511);
        float4 v = reinterpret_cast<const float4*>(x)[t];
        const int kg = i * 512 + k;
        ushort4 h;
        __half h0 = __float2half_rn(v.x);
        __half h1 = __float2half_rn(v.y);
        __half h2 = __float2half_rn(v.z);
        __half h3 = __float2half_rn(v.w);
        h.x = *reinterpret_cast<unsigned short*>(&h0);
        h.y = *reinterpret_cast<unsigned short*>(&h1);
        h.z = *reinterpret_cast<unsigned short*>(&h2);
        h.w = *reinterpret_cast<unsigned short*>(&h3);
        *reinterpret_cast<ushort4*>(A16 + (size_t)m * 2048 + kg) = h;
    } else {
        // W: [4][4][512][2048] (d,i,k,n) -> B16 fp16 [4][n][kg] (transpose)
        __shared__ float tile[32][33];
        const int bid2 = blockIdx.x - 16384;
        const int n0 = (bid2 & 63) * 32;
        const int k0 = ((bid2 >> 6) & 15) * 32;
        const int di = bid2 >> 10;
        const int d = di >> 2, i = di & 3;
        const int tx = tid & 31, ty = tid >> 5;     // 32 x 8
        const float* Wdi = W + (size_t)di * 512 * 2048;
#pragma unroll
        for (int j = 0; j < 32; j += 8)
            tile[ty + j][tx] = Wdi[(size_t)(k0 + ty + j) * 2048 + n0 + tx];
        __syncthreads();
        size_t obase = (size_t)d * 2048 * 2048;
#pragma unroll
        for (int j = 0; j < 32; j += 8) {
            float v = tile[tx][ty + j];
            __half hv = __float2half_rn(v);
            const int n = n0 + ty + j;
            const int kg = i * 512 + k0 + tx;
            B16[obase + (size_t)n * 2048 + kg] = hv;
        }
    }
}

// ------------------------------ GEMM kernel --------------------------------
__global__ __launch_bounds__(192, 1) __cluster_dims__(4, 1, 1)
void tp_gemm_kernel(const __grid_constant__ CUtensorMap tmA,
                    const __grid_constant__ CUtensorMap tmB,
                    const float* __restrict__ bias,
                    float* __restrict__ out,
                    int nClusters) {
#if TC_OK
    extern __shared__ char smem[];
    const uint32_t sb = smem_u32(smem);
    const int tid = threadIdx.x;
    const int wid = tid >> 5;
    const int lid = tid & 31;
    const uint32_t rank = cluster_rank();
    const int pr = (int)(rank >> 1);       // cg2 pair index (0,1)
    const int wr = (int)(rank & 1);        // rank within pair
    const int pairLeader = pr * 2;
    const uint16_t pairMask = (uint16_t)(0x3u << (pr * 2));
    const int clu = (int)(blockIdx.x >> 2);

    if (wid == 0) {
        TC_ALLOC_CG2(sb + OFF_TMEM, 512);
        TC_RELINQ_CG2();
    }
    if (tid == 0) {
#pragma unroll
        for (int s = 0; s < STAGES; s++) {
            // leader full: expect arrive + relay arrive = 2; odd CTAs: expect only
            MBAR_INIT(sb + OFF_FULL + 8 * s, wr ? 1 : 2);
            // empty: both pair leaders' commits (mask 0xF)
            MBAR_INIT(sb + OFF_EMPTY + 8 * s, 2);
        }
#pragma unroll
        for (int b = 0; b < 2; b++) {
            MBAR_INIT(sb + OFF_ACCDONE + 8 * b, 1);
            MBAR_INIT(sb + OFF_ACCFREE + 8 * b, 8);   // 4 warps x 2 CTAs of pair
        }
    }
    __syncthreads();
    CLUSTER_SYNC();

    uint32_t tmem;
    asm volatile("ld.shared.b32 %0, [%1];" : "=r"(tmem) : "r"(sb + OFF_TMEM));

    if (wid == 0) {
        // ------- producer (all CTAs): A cg2 x2; B multicast x2 from ranks 0,1 ----
        int ps = 0; uint32_t pp = 1;
        for (int t = clu; t < NPAIRS; t += nClusters) {
            const int nIdx = t & 7;
            const int mIdx = (t >> 3) & 15;
            const int d    = t >> 7;
            const int mRow = mIdx * 512 + pr * 256 + wr * 128;
            const int nRow = nIdx * 256 + wr * 128;
            for (int chunk = 0; chunk < NCHUNK; chunk++) {
                mbar_wait_rel(sb + OFF_EMPTY + 8 * ps, pp);
                if (elect_one()) {
                    const uint32_t fb = sb + OFF_FULL + 8 * ps;
                    const uint32_t stg = sb + OFF_STG + ps * STG_BYTES;
                    const int kc = chunk * KB;
                    if (wr == 0)
                        MBAR_EXPECT_TX(fb, CHUNK_TX);    // 96K on pair leaders
                    tma_load_cg2(stg + SO_A,              &tmA, kc,      mRow, 0, fb);
                    tma_load_cg2(stg + SO_A + HALF_BYTES, &tmA, kc + 64, mRow, 0, fb);
                    if (rank == 0) {
                        tma_mcast_3d(stg + SO_B,              &tmB, kc,      nRow, d, fb, 0x5);
                        tma_mcast_3d(stg + SO_B + HALF_BYTES, &tmB, kc + 64, nRow, d, fb, 0x5);
                    } else if (rank == 1) {
                        tma_mcast_3d(stg + SO_B,              &tmB, kc,      nRow, d, fb, 0xA);
                        tma_mcast_3d(stg + SO_B + HALF_BYTES, &tmB, kc + 64, nRow, d, fb, 0xA);
                    }
                }
                if (++ps == STAGES) { ps = 0; pp ^= 1; }
            }
        }
    } else if (wid == 1 && wr == 1) {
        // ------- relay (ranks 1,3): forward local B completion to pair leader ---
        int rs = 0; uint32_t rp = 0;
        for (int t = clu; t < NPAIRS; t += nClusters) {
            for (int chunk = 0; chunk < NCHUNK; chunk++) {
                const uint32_t fb = sb + OFF_FULL + 8 * rs;
                if (elect_one())
                    MBAR_EXPECT_TX(fb, OP_BYTES);        // 32K B (2 halves)
                mbar_wait_acq(fb, rp);
                if (elect_one())
                    MBAR_ARRIVE_RANK(fb, pairLeader);
                if (++rs == STAGES) { rs = 0; rp ^= 1; }
            }
        }
    } else if (wid == 1) {
        // ------- consumer (pair leaders, ranks 0,2): 8 k-steps per wait -------
        uint64_t adS[STAGES], bdS[STAGES];
#pragma unroll
        for (int s = 0; s < STAGES; s++) {
            const uint32_t stg = sb + OFF_STG + s * STG_BYTES;
            adS[s] = DESC_BASE_SW128 | ((uint64_t)((stg + SO_A) >> 4) & 0x3FFF);
            bdS[s] = DESC_BASE_SW128 | ((uint64_t)((stg + SO_B) >> 4) & 0x3FFF);
        }
        int cs = 0; uint32_t cp = 0;
        uint32_t tIdx = 0;
        for (int t = clu; t < NPAIRS; t += nClusters, tIdx++) {
            const int b = tIdx & 1;
            mbar_wait_rel(sb + OFF_ACCFREE + 8 * b, ((tIdx >> 1) & 1) ^ 1);
            TC_FENCE_AFTER();
            const uint32_t dtm = tmem + b * 256;
            for (int chunk = 0; chunk < NCHUNK; chunk++) {
                mbar_wait_acq(sb + OFF_FULL + 8 * cs, cp);
                if (elect_one()) {
                    const uint64_t ad = adS[cs];
                    const uint64_t bd = bdS[cs];
#pragma unroll
                    for (int ks = 0; ks < 8; ks++) {
                        const uint32_t en = (chunk != 0 || ks != 0) ? 1u : 0u;
                        const uint64_t o = kstep_off(ks);
                        mma_f16_cg2(dtm, ad + o, bd + o, IDESC_F16, en);
                    }
                    TC_COMMIT_MC_CG2(sb + OFF_EMPTY + 8 * cs, 0xF);
                    if (chunk == NCHUNK - 1)
                        TC_COMMIT_MC_CG2(sb + OFF_ACCDONE + 8 * b, pairMask);
                }
                if (++cs == STAGES) { cs = 0; cp ^= 1; }
            }
        }
    } else {
        // ------- epilogue (all CTAs): 4 warps, own TMEM half -------
        const int sp = wid & 3;
        uint32_t tIdx = 0;
        for (int t = clu; t < NPAIRS; t += nClusters, tIdx++) {
            const int b = tIdx & 1;
            const int nIdx = t & 7;
            const int mIdx = (t >> 3) & 15;
            const int d    = t >> 7;
            const int nB = nIdx * 256;

            mbar_wait_acq(sb + OFF_ACCDONE + 8 * b, (tIdx >> 1) & 1);
            TC_FENCE_AFTER();

            const int mRow = mIdx * 512 + pr * 256 + wr * 128 + sp * 32 + lid;
            float* orow = out + ((size_t)d * M_TOT + mRow) * N_TOT + nB;
            const float* brow = bias + d * N_TOT + nB;
            const uint32_t tbase = tmem + b * 256;

#pragma unroll
            for (int nb = 0; nb < 256; nb += 32) {
                uint32_t r[32];
                TC_LD_X32(r, tbase + nb);
                TC_WAIT_LD();
#pragma unroll
                for (int j = 0; j < 32; j += 4) {
                    const float4 bv = *reinterpret_cast<const float4*>(brow + nb + j);
                    float4 v;
                    v.x = __uint_as_float(r[j + 0]) + bv.x;
                    v.y = __uint_as_float(r[j + 1]) + bv.y;
                    v.z = __uint_as_float(r[j + 2]) + bv.z;
                    v.w = __uint_as_float(r[j + 3]) + bv.w;
                    *reinterpret_cast<float4*>(orow + nb + j) = v;
                }
            }
            TC_FENCE_BEFORE();
            if (lid == 0)
                MBAR_ARRIVE_RANK(sb + OFF_ACCFREE + 8 * b, pairLeader);
        }
    }

    __syncthreads();
    if (tid == 0) {
#pragma unroll
        for (int s = 0; s < STAGES; s++) {
            MBAR_INVAL(sb + OFF_FULL + 8 * s);
            MBAR_INVAL(sb + OFF_EMPTY + 8 * s);
        }
#pragma unroll
        for (int b = 0; b < 2; b++) {
            MBAR_INVAL(sb + OFF_ACCDONE + 8 * b);
            MBAR_INVAL(sb + OFF_ACCFREE + 8 * b);
        }
    }
    __syncthreads();
    CLUSTER_SYNC();
    if (wid == 0) {
        TC_DEALLOC_CG2(tmem, 512);
    }
    CLUSTER_SYNC();
#endif // TC_OK
}

// ------------------------------ host launch --------------------------------
typedef CUresult (*PFN_encodeTiled)(CUtensorMap*, CUtensorMapDataType, cuuint32_t, void*,
                                    const cuuint64_t*, const cuuint64_t*, const cuuint32_t*,
                                    const cuuint32_t*, CUtensorMapInterleave, CUtensorMapSwizzle,
                                    CUtensorMapL2promotion, CUtensorMapFloatOOBfill);

static void make_map_f16(PFN_encodeTiled enc, CUtensorMap* m, void* p,
                         uint64_t d0, uint64_t d1, uint64_t d2,
                         uint64_t s1b, uint64_t s2b, uint32_t b0, uint32_t b1) {
    cuuint64_t dims[3] = {d0, d1, d2};
    cuuint64_t strides[2] = {s1b, s2b};
    cuuint32_t box[3] = {b0, b1, 1};
    cuuint32_t es[3] = {1, 1, 1};
    enc(m, CU_TENSOR_MAP_DATA_TYPE_FLOAT16, 3, p, dims, strides, box, es,
        CU_TENSOR_MAP_INTERLEAVE_NONE, CU_TENSOR_MAP_SWIZZLE_128B,
        CU_TENSOR_MAP_L2_PROMOTION_L2_128B, CU_TENSOR_MAP_FLOAT_OOB_FILL_NONE);
}

extern "C" void kernel_launch(void* const* d_in, const int* in_sizes, int n_in,
                              void* d_out, int out_size) {
    const float* x    = (const float*)d_in[0];
    const float* W    = (const float*)d_in[1];
    const float* bias = (const float*)d_in[2];
    float* out        = (float*)d_out;

    void *pA, *pB;
    cudaGetSymbolAddress(&pA, g_A16);
    cudaGetSymbolAddress(&pB, g_B16);

    void* fp = nullptr;
    cudaDriverEntryPointQueryResult qr;
    cudaGetDriverEntryPoint("cuTensorMapEncodeTiled", &fp, cudaEnableDefault, &qr);
    PFN_encodeTiled enc = (PFN_encodeTiled)fp;

    CUtensorMap mA, mB;
    // A16: dims {K=2048, M=8192, 1}; box {64, 128}
    make_map_f16(enc, &mA, pA, K_TOT, M_TOT, 1,
                 (uint64_t)K_TOT * 2, (uint64_t)M_TOT * K_TOT * 2, 64, 128);
    // B16: dims {K=2048, N=2048, D=4}; box {64, 128}
    make_map_f16(enc, &mB, pB, K_TOT, N_TOT, D_TOT,
                 (uint64_t)K_TOT * 2, (uint64_t)N_TOT * K_TOT * 2, 64, 128);

    prep_kernel<<<32768, 256>>>(x, W, (__half*)pA, (__half*)pB);

    int dev = 0, sms = 148;
    cudaGetDevice(&dev);
    cudaDeviceGetAttribute(&sms, cudaDevAttrMultiProcessorCount, dev);
    int nBlocks = ((sms - 8) / 4) * 4;       // 152 -> 144 (36 clusters)
    if (nBlocks > 144) nBlocks = 144;
    int nClusters = nBlocks / 4;

    cudaFuncSetAttribute(tp_gemm_kernel, cudaFuncAttributeMaxDynamicSharedMemorySize,
                         SMEM_TOTAL);
    tp_gemm_kernel<<<nBlocks, 192, SMEM_TOTAL>>>(mA, mB, bias, out, nClusters);
}

// round 16
// speedup vs baseline: 1.0372x; 1.0372x over previous
#include <cuda_runtime.h>
#include <cuda.h>
#include <cuda_fp16.h>
#include <cstdint>

// ---------------------------------------------------------------------------
// TPAsyncDense, persistent cg2 clusters, fp16 GEMM, KB=128, split barriers:
//   y[d] = sum_i x_i @ W[d,i] + b[d]
// R16 = R14 (best, 244us) with each stage's full barrier split into two
// half-chunk barriers: {A0,B0} -> bar(s,0), {A1,B1} -> bar(s,1) (64KB each).
// Consumer waits h0 -> 4 MMAs -> waits h1 -> 4 MMAs -> one commit.
// Purpose: halve the consumer's wait-latency exposure per chunk. This is the
// discriminating experiment between "wait-latency gap" (expect ~15-20us win)
// and "SS-mode MMA pacing ceiling" (expect neutral; tensor busy stuck ~60%).
// Everything else identical to R14: cg2 256x256 tiles, TMEM 2x256 ping-pong,
// 3 stages x 64KB, 8 k-steps per commit, persistent grid 152.
// ---------------------------------------------------------------------------

#if defined(__CUDA_ARCH_FEAT_SM103_ALL) || defined(__CUDA_ARCH_FEAT_SM100_ALL) || \
    defined(__CUDA_ARCH_SPECIFIC__) || defined(__CUDA_ARCH_FAMILY_SPECIFIC__)
#define TC_OK 1
#else
#define TC_OK 0
#endif

#define M_TOT 8192
#define N_TOT 2048
#define K_TOT 2048
#define D_TOT 4

#define BM 256                     // per cluster (128 per CTA)
#define BN 256
#define KB 128                     // K elems per chunk (2 SW128 subtiles)
#define NCHUNK 16                  // 2048/128
#define STAGES 3
#define NTILES (D_TOT * (M_TOT / BM) * (N_TOT / BN))   // 1024

#define OFF_TMEM     0
#define OFF_FULL     16            // 6 x 8B (2 half-barriers per stage)
#define OFF_EMPTY    64            // 3 x 8B
#define OFF_ACCDONE  88            // 2 x 8B
#define OFF_ACCFREE  104           // 2 x 8B
#define HALF_BYTES   16384         // one 64-wide SW128 subtile (128 rows)
#define OP_BYTES     (2 * HALF_BYTES)               // 32768 per operand
#define STG_BYTES    (2 * OP_BYTES)                 // 65536 {A, B}
#define OFF_STG      1024
#define SMEM_TOTAL   (OFF_STG + STAGES * STG_BYTES) // 197632
#define HALF_TX      (2 * OP_BYTES / 1)             // placeholder (see below)
// per half-chunk, arriving on the leader barrier: A-half from both CTAs
// (2 x 16K) + B-half from both CTAs (2 x 16K) = 64K
#define HCHUNK_TX    (4 * HALF_BYTES)               // 65536

#define SO_A 0
#define SO_B OP_BYTES

// cg2 idesc: dtype=F32(1<<4), atype=btype=FP16(0), N=256, M=256
#define IDESC_F16 ((1u<<4) | (32u<<17) | (16u<<24))

static constexpr uint64_t DESC_BASE_SW128 =
    (uint64_t(2) << 61) | (uint64_t(1) << 46) | (uint64_t(64) << 32) | (uint64_t(1) << 16);
// k-step desc offset: steps 0-3 in first 16KB subtile (+2), steps 4-7 in
// second subtile (+1024 units = 16KB)
__device__ __forceinline__ uint64_t kstep_off(int ks) {
    return (uint64_t)((ks >> 2) * 1024 + (ks & 3) * 2);
}

// ------------------------- scratch (static device mem) ---------------------
__device__ __align__(1024) __half g_A16[(size_t)M_TOT * K_TOT];
__device__ __align__(1024) __half g_B16[(size_t)D_TOT * N_TOT * K_TOT];

// ------------------------------ PTX helpers --------------------------------
__device__ __forceinline__ uint32_t smem_u32(const void* p) {
    uint32_t a;
    asm("{ .reg .u64 t; cvta.to.shared.u64 t, %1; cvt.u32.u64 %0, t; }" : "=r"(a) : "l"(p));
    return a;
}
__device__ __forceinline__ uint32_t elect_one() {
    uint32_t pred;
    asm volatile("{\n\t.reg .pred p;\n\telect.sync _|p, 0xFFFFFFFF;\n\tselp.b32 %0, 1, 0, p;\n\t}"
                 : "=r"(pred));
    return pred;
}
__device__ __forceinline__ uint32_t cluster_rank() {
    uint32_t r;
    asm("mov.u32 %0, %%cluster_ctarank;" : "=r"(r));
    return r;
}
#define CLUSTER_SYNC() do { \
    asm volatile("barrier.cluster.arrive.aligned;" ::: "memory"); \
    asm volatile("barrier.cluster.wait.aligned;" ::: "memory"); \
} while (0)

#define MBAR_INIT(addr, cnt) \
    asm volatile("mbarrier.init.shared.b64 [%0], %1;" :: "r"(addr), "r"(cnt) : "memory")
#define MBAR_INVAL(addr) \
    asm volatile("mbarrier.inval.shared.b64 [%0];" :: "r"(addr) : "memory")
#define MBAR_EXPECT_TX(addr, bytes) \
    asm volatile("mbarrier.arrive.expect_tx.shared.b64 _, [%0], %1;" :: "r"(addr), "r"(bytes) : "memory")
#define MBAR_ARRIVE_RANK0(addr) \
    asm volatile("{\n\t.reg .b32 ra;\n\tmapa.shared::cluster.u32 ra, %0, 0;\n\t" \
                 "mbarrier.arrive.shared::cluster.b64 _, [ra];\n\t}" \
                 :: "r"(addr) : "memory")

__device__ __forceinline__ void mbar_wait_acq(uint32_t mbar, uint32_t parity) {
    asm volatile(
        "{\n\t.reg .pred P1;\n\t"
        "WAIT_LOOP_%=:\n\t"
        "mbarrier.try_wait.parity.acquire.cta.shared::cta.b64 P1, [%0], %1, 0x989680;\n\t"
        "@P1 bra.uni WAIT_DONE_%=;\n\t"
        "bra.uni WAIT_LOOP_%=;\n\t"
        "WAIT_DONE_%=:\n\t}"
        :: "r"(mbar), "r"(parity) : "memory");
}
__device__ __forceinline__ void mbar_wait_rel(uint32_t mbar, uint32_t parity) {
    asm volatile(
        "{\n\t.reg .pred P1;\n\t"
        "WAIT_LOOP_%=:\n\t"
        "mbarrier.try_wait.parity.relaxed.cta.shared::cta.b64 P1, [%0], %1, 0x989680;\n\t"
        "@P1 bra.uni WAIT_DONE_%=;\n\t"
        "bra.uni WAIT_LOOP_%=;\n\t"
        "WAIT_DONE_%=:\n\t}"
        :: "r"(mbar), "r"(parity) : "memory");
}

#if TC_OK
__device__ __forceinline__ void tma_load_cg2(uint32_t smem_dst, const CUtensorMap* map,
                                             int cx, int cy, int cz, uint32_t mbar) {
    asm volatile(
        "{\n\t.reg .b32 lb;\n\t"
        "and.b32 lb, %5, 0xFEFFFFFF;\n\t"
        "cp.async.bulk.tensor.3d.cta_group::2.shared::cluster.global"
        ".tile.mbarrier::complete_tx::bytes [%0], [%1, {%2, %3, %4}], [lb];\n\t}"
        :: "r"(smem_dst), "l"(map), "r"(cx), "r"(cy), "r"(cz), "r"(mbar) : "memory");
}

__device__ __forceinline__ void mma_f16_cg2(uint32_t dtm, uint64_t adesc, uint64_t bdesc,
                                            uint32_t idesc, uint32_t en) {
    asm volatile(
        "{\n\t.reg .pred p;\n\tsetp.ne.u32 p, %5, 0;\n\t"
        "tcgen05.mma.cta_group::2.kind::f16 [%0], %1, %2, %3, "
        "{%4, %4, %4, %4, %4, %4, %4, %4}, p;\n\t}"
        :: "r"(dtm), "l"(adesc), "l"(bdesc), "r"(idesc), "r"(0u), "r"(en) : "memory");
}

#define TC_ALLOC_CG2(smem_addr, cols) \
    asm volatile("tcgen05.alloc.cta_group::2.sync.aligned.shared::cta.b32 [%0], %1;" \
                 :: "r"(smem_addr), "r"(cols) : "memory")
#define TC_DEALLOC_CG2(tmem, cols) \
    asm volatile("tcgen05.dealloc.cta_group::2.sync.aligned.b32 %0, %1;" :: "r"(tmem), "r"(cols))
#define TC_RELINQ_CG2() \
    asm volatile("tcgen05.relinquish_alloc_permit.cta_group::2.sync.aligned;")
#define TC_COMMIT_MC_CG2(mbar) \
    asm volatile("tcgen05.commit.cta_group::2.mbarrier::arrive::one.shared::cluster" \
                 ".multicast::cluster.b64 [%0], %1;" \
                 :: "r"(mbar), "h"((uint16_t)0x3) : "memory")
#define TC_FENCE_AFTER() asm volatile("tcgen05.fence::after_thread_sync;" ::: "memory")
#define TC_FENCE_BEFORE() asm volatile("tcgen05.fence::before_thread_sync;" ::: "memory")
#define TC_WAIT_LD() asm volatile("tcgen05.wait::ld.sync.aligned;" ::: "memory")

#define TC_LD_X32(r, tm) \
    asm volatile( \
        "tcgen05.ld.sync.aligned.32x32b.x32.b32 " \
        "{%0, %1, %2, %3, %4, %5, %6, %7, " \
        " %8, %9, %10, %11, %12, %13, %14, %15, " \
        " %16, %17, %18, %19, %20, %21, %22, %23, " \
        " %24, %25, %26, %27, %28, %29, %30, %31}, [%32];" \
        : "=r"((r)[0]),  "=r"((r)[1]),  "=r"((r)[2]),  "=r"((r)[3]), \
          "=r"((r)[4]),  "=r"((r)[5]),  "=r"((r)[6]),  "=r"((r)[7]), \
          "=r"((r)[8]),  "=r"((r)[9]),  "=r"((r)[10]), "=r"((r)[11]), \
          "=r"((r)[12]), "=r"((r)[13]), "=r"((r)[14]), "=r"((r)[15]), \
          "=r"((r)[16]), "=r"((r)[17]), "=r"((r)[18]), "=r"((r)[19]), \
          "=r"((r)[20]), "=r"((r)[21]), "=r"((r)[22]), "=r"((r)[23]), \
          "=r"((r)[24]), "=r"((r)[25]), "=r"((r)[26]), "=r"((r)[27]), \
          "=r"((r)[28]), "=r"((r)[29]), "=r"((r)[30]), "=r"((r)[31]) \
        : "r"(tm))
#endif // TC_OK

// ------------------------------ fused prep ---------------------------------
__global__ void prep_kernel(const float* __restrict__ x,
                            const float* __restrict__ W,
                            __half* __restrict__ A16,
                            __half* __restrict__ B16) {
    const int tid = threadIdx.x;
    if (blockIdx.x < 16384) {
        // x: [4][8192][512] f32 -> A16 fp16 [8192][2048] (K = shard*512 + k)
        size_t t = (size_t)blockIdx.x * 256 + tid;
        size_t e = t * 4;
        int i = (int)(e >> 22);
        int m = (int)((e >> 9) & 8191);
        int k = (int)(e & 511);
        float4 v = reinterpret_cast<const float4*>(x)[t];
        const int kg = i * 512 + k;
        ushort4 h;
        __half h0 = __float2half_rn(v.x);
        __half h1 = __float2half_rn(v.y);
        __half h2 = __float2half_rn(v.z);
        __half h3 = __float2half_rn(v.w);
        h.x = *reinterpret_cast<unsigned short*>(&h0);
        h.y = *reinterpret_cast<unsigned short*>(&h1);
        h.z = *reinterpret_cast<unsigned short*>(&h2);
        h.w = *reinterpret_cast<unsigned short*>(&h3);
        *reinterpret_cast<ushort4*>(A16 + (size_t)m * 2048 + kg) = h;
    } else {
        // W: [4][4][512][2048] (d,i,k,n) -> B16 fp16 [4][n][kg] (transpose)
        __shared__ float tile[32][33];
        const int bid2 = blockIdx.x - 16384;
        const int n0 = (bid2 & 63) * 32;
        const int k0 = ((bid2 >> 6) & 15) * 32;
        const int di = bid2 >> 10;
        const int d = di >> 2, i = di & 3;
        const int tx = tid & 31, ty = tid >> 5;     // 32 x 8
        const float* Wdi = W + (size_t)di * 512 * 2048;
#pragma unroll
        for (int j = 0; j < 32; j += 8)
            tile[ty + j][tx] = Wdi[(size_t)(k0 + ty + j) * 2048 + n0 + tx];
        __syncthreads();
        size_t obase = (size_t)d * 2048 * 2048;
#pragma unroll
        for (int j = 0; j < 32; j += 8) {
            float v = tile[tx][ty + j];
            __half hv = __float2half_rn(v);
            const int n = n0 + ty + j;
            const int kg = i * 512 + k0 + tx;
            B16[obase + (size_t)n * 2048 + kg] = hv;
        }
    }
}

// ------------------------------ GEMM kernel --------------------------------
__global__ __launch_bounds__(192, 1) __cluster_dims__(2, 1, 1)
void tp_gemm_kernel(const __grid_constant__ CUtensorMap tmA,
                    const __grid_constant__ CUtensorMap tmB,
                    const float* __restrict__ bias,
                    float* __restrict__ out,
                    int nClusters) {
#if TC_OK
    extern __shared__ char smem[];
    const uint32_t sb = smem_u32(smem);
    const int tid = threadIdx.x;
    const int wid = tid >> 5;
    const int lid = tid & 31;
    const uint32_t rank = cluster_rank();
    const int clu = (int)(blockIdx.x >> 1);

    if (wid == 0) {
        TC_ALLOC_CG2(sb + OFF_TMEM, 512);
        TC_RELINQ_CG2();
    }
    if (tid == 0) {
#pragma unroll
        for (int s = 0; s < STAGES; s++) {
            MBAR_INIT(sb + OFF_FULL + 8 * (2 * s + 0), 1);
            MBAR_INIT(sb + OFF_FULL + 8 * (2 * s + 1), 1);
            MBAR_INIT(sb + OFF_EMPTY + 8 * s, 1);
        }
#pragma unroll
        for (int b = 0; b < 2; b++) {
            MBAR_INIT(sb + OFF_ACCDONE + 8 * b, 1);
            MBAR_INIT(sb + OFF_ACCFREE + 8 * b, 8);   // 4 warps x 2 CTAs
        }
    }
    __syncthreads();
    CLUSTER_SYNC();

    uint32_t tmem;
    asm volatile("ld.shared.b32 %0, [%1];" : "=r"(tmem) : "r"(sb + OFF_TMEM));

    if (wid == 0) {
        // ------- producer (both CTAs): 4 cg2 TMA loads, split over 2 bars ----
        int ps = 0; uint32_t pp = 1;
        for (int t = clu; t < NTILES; t += nClusters) {
            const int nIdx = t & 7;
            const int mIdx = (t >> 3) & 31;
            const int d    = t >> 8;
            const int mRow = mIdx * BM + (int)rank * 128;     // own A half
            const int nRow = nIdx * BN + (int)rank * 128;     // own B half (cg2)
            for (int chunk = 0; chunk < NCHUNK; chunk++) {
                mbar_wait_rel(sb + OFF_EMPTY + 8 * ps, pp);
                if (elect_one()) {
                    const uint32_t fb0 = sb + OFF_FULL + 8 * (2 * ps + 0);
                    const uint32_t fb1 = sb + OFF_FULL + 8 * (2 * ps + 1);
                    const uint32_t stg = sb + OFF_STG + ps * STG_BYTES;
                    const int kc = chunk * KB;
                    if (rank == 0) {
                        MBAR_EXPECT_TX(fb0, HCHUNK_TX);
                        MBAR_EXPECT_TX(fb1, HCHUNK_TX);
                    }
                    // half 0: k [kc, kc+64)
                    tma_load_cg2(stg + SO_A,              &tmA, kc,      mRow, 0, fb0);
                    tma_load_cg2(stg + SO_B,              &tmB, kc,      nRow, d, fb0);
                    // half 1: k [kc+64, kc+128)
                    tma_load_cg2(stg + SO_A + HALF_BYTES, &tmA, kc + 64, mRow, 0, fb1);
                    tma_load_cg2(stg + SO_B + HALF_BYTES, &tmB, kc + 64, nRow, d, fb1);
                }
                if (++ps == STAGES) { ps = 0; pp ^= 1; }
            }
        }
    } else if (wid == 1 && rank == 0) {
        // ------- consumer (rank 0): wait h0 -> 4 MMAs -> wait h1 -> 4 MMAs ----
        uint64_t adS[STAGES], bdS[STAGES];
#pragma unroll
        for (int s = 0; s < STAGES; s++) {
            const uint32_t stg = sb + OFF_STG + s * STG_BYTES;
            adS[s] = DESC_BASE_SW128 | ((uint64_t)((stg + SO_A) >> 4) & 0x3FFF);
            bdS[s] = DESC_BASE_SW128 | ((uint64_t)((stg + SO_B) >> 4) & 0x3FFF);
        }
        int cs = 0; uint32_t cp = 0;
        uint32_t tIdx = 0;
        for (int t = clu; t < NTILES; t += nClusters, tIdx++) {
            const int b = tIdx & 1;
            mbar_wait_rel(sb + OFF_ACCFREE + 8 * b, ((tIdx >> 1) & 1) ^ 1);
            TC_FENCE_AFTER();
            const uint32_t dtm = tmem + b * 256;
            for (int chunk = 0; chunk < NCHUNK; chunk++) {
                const uint64_t ad = adS[cs];
                const uint64_t bd = bdS[cs];
                // half 0
                mbar_wait_acq(sb + OFF_FULL + 8 * (2 * cs + 0), cp);
                if (elect_one()) {
#pragma unroll
                    for (int ks = 0; ks < 4; ks++) {
                        const uint32_t en = (chunk != 0 || ks != 0) ? 1u : 0u;
                        const uint64_t o = kstep_off(ks);
                        mma_f16_cg2(dtm, ad + o, bd + o, IDESC_F16, en);
                    }
                }
                // half 1
                mbar_wait_acq(sb + OFF_FULL + 8 * (2 * cs + 1), cp);
                if (elect_one()) {
#pragma unroll
                    for (int ks = 4; ks < 8; ks++) {
                        const uint64_t o = kstep_off(ks);
                        mma_f16_cg2(dtm, ad + o, bd + o, IDESC_F16, 1u);
                    }
                    TC_COMMIT_MC_CG2(sb + OFF_EMPTY + 8 * cs);
                    if (chunk == NCHUNK - 1)
                        TC_COMMIT_MC_CG2(sb + OFF_ACCDONE + 8 * b);
                }
                if (++cs == STAGES) { cs = 0; cp ^= 1; }
            }
        }
    } else if (wid >= 2) {
        // ------- epilogue (both CTAs): 4 warps, own TMEM half -------
        const int sp = wid & 3;
        uint32_t tIdx = 0;
        for (int t = clu; t < NTILES; t += nClusters, tIdx++) {
            const int b = tIdx & 1;
            const int nIdx = t & 7;
            const int mIdx = (t >> 3) & 31;
            const int d    = t >> 8;
            const int nB = nIdx * BN;

            mbar_wait_acq(sb + OFF_ACCDONE + 8 * b, (tIdx >> 1) & 1);
            TC_FENCE_AFTER();

            const int mRow = mIdx * BM + (int)rank * 128 + sp * 32 + lid;
            float* orow = out + ((size_t)d * M_TOT + mRow) * N_TOT + nB;
            const float* brow = bias + d * N_TOT + nB;
            const uint32_t tbase = tmem + b * 256;

#pragma unroll
            for (int nb = 0; nb < BN; nb += 32) {
                uint32_t r[32];
                TC_LD_X32(r, tbase + nb);
                TC_WAIT_LD();
#pragma unroll
                for (int j = 0; j < 32; j += 4) {
                    const float4 bv = *reinterpret_cast<const float4*>(brow + nb + j);
                    float4 v;
                    v.x = __uint_as_float(r[j + 0]) + bv.x;
                    v.y = __uint_as_float(r[j + 1]) + bv.y;
                    v.z = __uint_as_float(r[j + 2]) + bv.z;
                    v.w = __uint_as_float(r[j + 3]) + bv.w;
                    *reinterpret_cast<float4*>(orow + nb + j) = v;
                }
            }
            TC_FENCE_BEFORE();
            if (lid == 0)
                MBAR_ARRIVE_RANK0(sb + OFF_ACCFREE + 8 * b);
        }
    }

    __syncthreads();
    if (tid == 0) {
#pragma unroll
        for (int s = 0; s < STAGES; s++) {
            MBAR_INVAL(sb + OFF_FULL + 8 * (2 * s + 0));
            MBAR_INVAL(sb + OFF_FULL + 8 * (2 * s + 1));
            MBAR_INVAL(sb + OFF_EMPTY + 8 * s);
        }
#pragma unroll
        for (int b = 0; b < 2; b++) {
            MBAR_INVAL(sb + OFF_ACCDONE + 8 * b);
            MBAR_INVAL(sb + OFF_ACCFREE + 8 * b);
        }
    }
    __syncthreads();
    CLUSTER_SYNC();
    if (wid == 0) {
        TC_DEALLOC_CG2(tmem, 512);
    }
    CLUSTER_SYNC();
#endif // TC_OK
}

// ------------------------------ host launch --------------------------------
typedef CUresult (*PFN_encodeTiled)(CUtensorMap*, CUtensorMapDataType, cuuint32_t, void*,
                                    const cuuint64_t*, const cuuint64_t*, const cuuint32_t*,
                                    const cuuint32_t*, CUtensorMapInterleave, CUtensorMapSwizzle,
                                    CUtensorMapL2promotion, CUtensorMapFloatOOBfill);

static void make_map_f16(PFN_encodeTiled enc, CUtensorMap* m, void* p,
                         uint64_t d0, uint64_t d1, uint64_t d2,
                         uint64_t s1b, uint64_t s2b, uint32_t b0, uint32_t b1) {
    cuuint64_t dims[3] = {d0, d1, d2};
    cuuint64_t strides[2] = {s1b, s2b};
    cuuint32_t box[3] = {b0, b1, 1};
    cuuint32_t es[3] = {1, 1, 1};
    enc(m, CU_TENSOR_MAP_DATA_TYPE_FLOAT16, 3, p, dims, strides, box, es,
        CU_TENSOR_MAP_INTERLEAVE_NONE, CU_TENSOR_MAP_SWIZZLE_128B,
        CU_TENSOR_MAP_L2_PROMOTION_L2_128B, CU_TENSOR_MAP_FLOAT_OOB_FILL_NONE);
}

extern "C" void kernel_launch(void* const* d_in, const int* in_sizes, int n_in,
                              void* d_out, int out_size) {
    const float* x    = (const float*)d_in[0];
    const float* W    = (const float*)d_in[1];
    const float* bias = (const float*)d_in[2];
    float* out        = (float*)d_out;

    void *pA, *pB;
    cudaGetSymbolAddress(&pA, g_A16);
    cudaGetSymbolAddress(&pB, g_B16);

    void* fp = nullptr;
    cudaDriverEntryPointQueryResult qr;
    cudaGetDriverEntryPoint("cuTensorMapEncodeTiled", &fp, cudaEnableDefault, &qr);
    PFN_encodeTiled enc = (PFN_encodeTiled)fp;

    CUtensorMap mA, mB;
    // A16: dims {K=2048, M=8192, 1}; box {64, 128}
    make_map_f16(enc, &mA, pA, K_TOT, M_TOT, 1,
                 (uint64_t)K_TOT * 2, (uint64_t)M_TOT * K_TOT * 2, 64, 128);
    // B16: dims {K=2048, N=2048, D=4}; box {64, 128}
    make_map_f16(enc, &mB, pB, K_TOT, N_TOT, D_TOT,
                 (uint64_t)K_TOT * 2, (uint64_t)N_TOT * K_TOT * 2, 64, 128);

    prep_kernel<<<32768, 256>>>(x, W, (__half*)pA, (__half*)pB);

    int dev = 0, sms = 148;
    cudaGetDevice(&dev);
    cudaDeviceGetAttribute(&sms, cudaDevAttrMultiProcessorCount, dev);
    int nBlocks = sms & ~1;
    int nClusters = nBlocks / 2;

    cudaFuncSetAttribute(tp_gemm_kernel, cudaFuncAttributeMaxDynamicSharedMemorySize,
                         SMEM_TOTAL);
    tp_gemm_kernel<<<nBlocks, 192, SMEM_TOTAL>>>(mA, mB, bias, out, nClusters);
}